// round 1
// baseline (speedup 1.0000x reference)
#include <cuda_runtime.h>
#include <cuda_bf16.h>

// Problem constants
#define NB 64      // batch
#define HH 256
#define WW 256
#define CIN 3
#define CC 32      // channels
#define KK 5
#define ADIM 4
#define AHID 256

// ---------------- scratch (allocation-free: __device__ globals) ----------------
__device__ float g_h1[NB * CC * 128 * 128];   // after conv1+relu  (134 MB)
__device__ float g_h2[NB * CC * 64 * 64];     // after conv2+relu  (33.5 MB)
__device__ float g_ker[NB * CC * KK * KK];    // per-sample kernels [64,32,5,5]
__device__ float g_sa[NB * CC * 64 * 64];     // after cross-conv
__device__ float g_f [NB * CC * 64 * 64];     // after mp1+relu

// =================== action encoder: 2-layer MLP ===================
// hidden = relu(act @ w1 + b1)  [64,256]; kernels = hidden @ w2 + b2 [64,800]
__global__ void ae_kernel(const float* __restrict__ act,
                          const float* __restrict__ w1, const float* __restrict__ b1,
                          const float* __restrict__ w2, const float* __restrict__ b2) {
    __shared__ float sH[AHID];
    __shared__ float sA[ADIM];
    int n = blockIdx.x, tid = threadIdx.x;   // 256 threads
    if (tid < ADIM) sA[tid] = act[n * ADIM + tid];
    __syncthreads();
    float h = b1[tid];
#pragma unroll
    for (int i = 0; i < ADIM; i++) h = fmaf(sA[i], w1[i * AHID + tid], h);
    sH[tid] = fmaxf(h, 0.f);
    __syncthreads();
    for (int o = tid; o < CC * KK * KK; o += 256) {
        float acc = b2[o];
#pragma unroll 8
        for (int j = 0; j < AHID; j++) acc = fmaf(sH[j], w2[j * (CC * KK * KK) + o], acc);
        g_ker[n * (CC * KK * KK) + o] = acc;
    }
}

// =================== conv1: 3->32, k5, s2, p2, NHWC input ===================
// out tile 32x8 per block, acc[32] per thread, weights smem [tap][oc]
__global__ void conv1_kernel(const float* __restrict__ img,
                             const float* __restrict__ w, const float* __restrict__ b) {
    __shared__ float sIn[3 * 19 * 67];
    __shared__ float sW[75 * 32];
    __shared__ float sB[32];
    int n = blockIdx.z;
    int ox0 = blockIdx.x * 32, oy0 = blockIdx.y * 8;
    int tid = threadIdx.x;

    for (int i = tid; i < 75 * 32; i += 256) {
        int o = i & 31, tap = i >> 5;
        int c = tap / 25, r = tap % 25, kh = r / 5, kw = r % 5;
        sW[i] = w[((o * 3 + c) * 5 + kh) * 5 + kw];
    }
    if (tid < 32) sB[tid] = b[tid];

    int iy0 = oy0 * 2 - 2, ix0 = ox0 * 2 - 2;
    for (int i = tid; i < 3 * 19 * 67; i += 256) {
        int c = i / (19 * 67), r = i % (19 * 67);
        int iy = r / 67, ix = r % 67;
        int gy = iy0 + iy, gx = ix0 + ix;
        float v = 0.f;
        if ((unsigned)gy < 256u && (unsigned)gx < 256u)
            v = img[((n * 256 + gy) * 256 + gx) * 3 + c];
        sIn[i] = v;
    }
    __syncthreads();

    int ox = tid & 31, oy = tid >> 5;
    float acc[32];
#pragma unroll
    for (int o = 0; o < 32; o++) acc[o] = sB[o];

    for (int c = 0; c < 3; c++)
        for (int kh = 0; kh < 5; kh++) {
            const float* row = &sIn[c * (19 * 67) + (oy * 2 + kh) * 67 + ox * 2];
#pragma unroll
            for (int kw = 0; kw < 5; kw++) {
                float v = row[kw];
                const float* wp = &sW[((c * 5 + kh) * 5 + kw) * 32];
#pragma unroll
                for (int o = 0; o < 32; o++) acc[o] = fmaf(v, wp[o], acc[o]);
            }
        }

    int gy = oy0 + oy, gx = ox0 + ox;
#pragma unroll
    for (int o = 0; o < 32; o++)
        g_h1[((n * 32 + o) * 128 + gy) * 128 + gx] = fmaxf(acc[o], 0.f);
}

// =================== conv2: 32->32, k5, s2, p2, NCHW ===================
__global__ void conv2_kernel(const float* __restrict__ w, const float* __restrict__ b) {
    __shared__ float sIn[19 * 67];
    __shared__ float sW[25 * 32];
    __shared__ float sB[32];
    int n = blockIdx.z;
    int ox0 = blockIdx.x * 32, oy0 = blockIdx.y * 8;
    int tid = threadIdx.x;
    int ox = tid & 31, oy = tid >> 5;

    if (tid < 32) sB[tid] = b[tid];
    __syncthreads();
    float acc[32];
#pragma unroll
    for (int o = 0; o < 32; o++) acc[o] = sB[o];

    int iy0 = oy0 * 2 - 2, ix0 = ox0 * 2 - 2;
    for (int ic = 0; ic < 32; ic++) {
        __syncthreads();
        for (int i = tid; i < 19 * 67; i += 256) {
            int iy = i / 67, ix = i % 67;
            int gy = iy0 + iy, gx = ix0 + ix;
            float v = 0.f;
            if ((unsigned)gy < 128u && (unsigned)gx < 128u)
                v = g_h1[((n * 32 + ic) * 128 + gy) * 128 + gx];
            sIn[i] = v;
        }
        for (int i = tid; i < 25 * 32; i += 256) {
            int o = i & 31, tap = i >> 5;
            sW[i] = w[(o * 32 + ic) * 25 + tap];
        }
        __syncthreads();
#pragma unroll
        for (int kh = 0; kh < 5; kh++) {
            const float* row = &sIn[(oy * 2 + kh) * 67 + ox * 2];
#pragma unroll
            for (int kw = 0; kw < 5; kw++) {
                float v = row[kw];
                const float* wp = &sW[(kh * 5 + kw) * 32];
#pragma unroll
                for (int o = 0; o < 32; o++) acc[o] = fmaf(v, wp[o], acc[o]);
            }
        }
    }
    int gy = oy0 + oy, gx = ox0 + ox;
#pragma unroll
    for (int o = 0; o < 32; o++)
        g_h2[((n * 32 + o) * 64 + gy) * 64 + gx] = fmaxf(acc[o], 0.f);
}

// =================== cross-conv: per-sample depthwise k5 p2 ===================
__global__ void xconv_kernel() {
    __shared__ float sIn[68 * 68];
    __shared__ float sK[25];
    int c = blockIdx.x, n = blockIdx.y;
    int tid = threadIdx.x;
    const float* src = &g_h2[(n * 32 + c) * 4096];
    for (int i = tid; i < 68 * 68; i += 256) {
        int iy = i / 68, ix = i % 68;
        int gy = iy - 2, gx = ix - 2;
        sIn[i] = ((unsigned)gy < 64u && (unsigned)gx < 64u) ? src[gy * 64 + gx] : 0.f;
    }
    if (tid < 25) sK[tid] = g_ker[(n * 32 + c) * 25 + tid];
    __syncthreads();
    float k[25];
#pragma unroll
    for (int t = 0; t < 25; t++) k[t] = sK[t];
    for (int p = tid; p < 4096; p += 256) {
        int y = p >> 6, x = p & 63;
        float acc = 0.f;
#pragma unroll
        for (int kh = 0; kh < 5; kh++)
#pragma unroll
            for (int kw = 0; kw < 5; kw++)
                acc = fmaf(sIn[(y + kh) * 68 + (x + kw)], k[kh * 5 + kw], acc);
        g_sa[(n * 32 + c) * 4096 + p] = acc;
    }
}

// =================== mp1: 32->32, k3, p1, relu ===================
__global__ void mp1_kernel(const float* __restrict__ w, const float* __restrict__ b) {
    __shared__ float sIn[10 * 34];
    __shared__ float sW[9 * 32];
    __shared__ float sB[32];
    int n = blockIdx.z;
    int ox0 = blockIdx.x * 32, oy0 = blockIdx.y * 8;
    int tid = threadIdx.x;
    int ox = tid & 31, oy = tid >> 5;

    if (tid < 32) sB[tid] = b[tid];
    __syncthreads();
    float acc[32];
#pragma unroll
    for (int o = 0; o < 32; o++) acc[o] = sB[o];

    int iy0 = oy0 - 1, ix0 = ox0 - 1;
    for (int ic = 0; ic < 32; ic++) {
        __syncthreads();
        for (int i = tid; i < 10 * 34; i += 256) {
            int iy = i / 34, ix = i % 34;
            int gy = iy0 + iy, gx = ix0 + ix;
            float v = 0.f;
            if ((unsigned)gy < 64u && (unsigned)gx < 64u)
                v = g_sa[((n * 32 + ic) * 64 + gy) * 64 + gx];
            sIn[i] = v;
        }
        for (int i = tid; i < 9 * 32; i += 256) {
            int o = i & 31, tap = i >> 5;
            sW[i] = w[(o * 32 + ic) * 9 + tap];
        }
        __syncthreads();
#pragma unroll
        for (int kh = 0; kh < 3; kh++) {
            const float* row = &sIn[(oy + kh) * 34 + ox];
#pragma unroll
            for (int kw = 0; kw < 3; kw++) {
                float v = row[kw];
                const float* wp = &sW[(kh * 3 + kw) * 32];
#pragma unroll
                for (int o = 0; o < 32; o++) acc[o] = fmaf(v, wp[o], acc[o]);
            }
        }
    }
    int gy = oy0 + oy, gx = ox0 + ox;
#pragma unroll
    for (int o = 0; o < 32; o++)
        g_f[((n * 32 + o) * 64 + gy) * 64 + gx] = fmaxf(acc[o], 0.f);
}

// =================== mp2: 32->2, k3, p1 (final flow) ===================
__global__ void mp2_kernel(const float* __restrict__ w, const float* __restrict__ b,
                           float* __restrict__ out) {
    __shared__ float sIn[10 * 34];
    __shared__ float sW[9 * 2];
    int n = blockIdx.z;
    int ox0 = blockIdx.x * 32, oy0 = blockIdx.y * 8;
    int tid = threadIdx.x;
    int ox = tid & 31, oy = tid >> 5;

    float acc0 = b[0], acc1 = b[1];
    int iy0 = oy0 - 1, ix0 = ox0 - 1;
    for (int ic = 0; ic < 32; ic++) {
        __syncthreads();
        for (int i = tid; i < 10 * 34; i += 256) {
            int iy = i / 34, ix = i % 34;
            int gy = iy0 + iy, gx = ix0 + ix;
            float v = 0.f;
            if ((unsigned)gy < 64u && (unsigned)gx < 64u)
                v = g_f[((n * 32 + ic) * 64 + gy) * 64 + gx];
            sIn[i] = v;
        }
        if (tid < 18) {
            int o = tid & 1, tap = tid >> 1;
            sW[tid] = w[(o * 32 + ic) * 9 + tap];
        }
        __syncthreads();
#pragma unroll
        for (int kh = 0; kh < 3; kh++) {
            const float* row = &sIn[(oy + kh) * 34 + ox];
#pragma unroll
            for (int kw = 0; kw < 3; kw++) {
                float v = row[kw];
                acc0 = fmaf(v, sW[(kh * 3 + kw) * 2 + 0], acc0);
                acc1 = fmaf(v, sW[(kh * 3 + kw) * 2 + 1], acc1);
            }
        }
    }
    int gy = oy0 + oy, gx = ox0 + ox;
    out[((n * 2 + 0) * 64 + gy) * 64 + gx] = acc0;
    out[((n * 2 + 1) * 64 + gy) * 64 + gx] = acc1;
}

// =================== launch ===================
extern "C" void kernel_launch(void* const* d_in, const int* in_sizes, int n_in,
                              void* d_out, int out_size) {
    const float* images = (const float*)d_in[0];
    const float* actions = (const float*)d_in[1];
    const float* pe_w1 = (const float*)d_in[2];
    const float* pe_b1 = (const float*)d_in[3];
    const float* pe_w2 = (const float*)d_in[4];
    const float* pe_b2 = (const float*)d_in[5];
    const float* ae_w1 = (const float*)d_in[6];
    const float* ae_b1 = (const float*)d_in[7];
    const float* ae_w2 = (const float*)d_in[8];
    const float* ae_b2 = (const float*)d_in[9];
    const float* mp_w1 = (const float*)d_in[10];
    const float* mp_b1 = (const float*)d_in[11];
    const float* mp_w2 = (const float*)d_in[12];
    const float* mp_b2 = (const float*)d_in[13];
    float* out = (float*)d_out;

    ae_kernel<<<NB, 256>>>(actions, ae_w1, ae_b1, ae_w2, ae_b2);
    conv1_kernel<<<dim3(4, 16, NB), 256>>>(images, pe_w1, pe_b1);
    conv2_kernel<<<dim3(2, 8, NB), 256>>>(pe_w2, pe_b2);
    xconv_kernel<<<dim3(32, NB), 256>>>();
    mp1_kernel<<<dim3(2, 8, NB), 256>>>(mp_w1, mp_b1);
    mp2_kernel<<<dim3(2, 8, NB), 256>>>(mp_w2, mp_b2, out);
}

// round 2
// speedup vs baseline: 1.4806x; 1.4806x over previous
#include <cuda_runtime.h>
#include <cuda_bf16.h>

#define NB 64
#define CC 32
#define KK 5
#define ADIM 4
#define AHID 256

// ---------------- scratch ----------------
__device__ float g_h1[NB * CC * 128 * 128];
__device__ float g_h2[NB * CC * 64 * 64];
__device__ float g_ker[NB * CC * KK * KK];
__device__ float g_sa[NB * CC * 64 * 64];
__device__ float g_f [NB * CC * 64 * 64];

// =================== action encoder MLP ===================
__global__ void ae_kernel(const float* __restrict__ act,
                          const float* __restrict__ w1, const float* __restrict__ b1,
                          const float* __restrict__ w2, const float* __restrict__ b2) {
    __shared__ float sH[AHID];
    __shared__ float sA[ADIM];
    int n = blockIdx.x, tid = threadIdx.x;
    if (tid < ADIM) sA[tid] = act[n * ADIM + tid];
    __syncthreads();
    float h = b1[tid];
#pragma unroll
    for (int i = 0; i < ADIM; i++) h = fmaf(sA[i], w1[i * AHID + tid], h);
    sH[tid] = fmaxf(h, 0.f);
    __syncthreads();
    for (int o = tid; o < CC * KK * KK; o += 256) {
        float acc = b2[o];
#pragma unroll 8
        for (int j = 0; j < AHID; j++) acc = fmaf(sH[j], w2[j * (CC * KK * KK) + o], acc);
        g_ker[n * (CC * KK * KK) + o] = acc;
    }
}

// =================== conv1: 3->32, k5, s2, p2, NHWC in ===================
// 32x16 output tile, 2 pixels/thread (vertical pair), weights+input loaded once.
__global__ void __launch_bounds__(256, 2)
conv1_kernel(const float* __restrict__ img,
             const float* __restrict__ w, const float* __restrict__ b) {
    __shared__ float sIn[3 * 35 * 67];   // 7035
    __shared__ float sW[75 * 32];        // 2400
    __shared__ float sB[32];
    int n = blockIdx.z;
    int ox0 = blockIdx.x * 32, oy0 = blockIdx.y * 16;
    int tid = threadIdx.x;

    for (int i = tid; i < 75 * 32; i += 256) {
        int o = i & 31, tap = i >> 5;
        int c = tap / 25, r = tap % 25, kh = r / 5, kw = r % 5;
        sW[i] = w[((o * 3 + c) * 5 + kh) * 5 + kw];
    }
    if (tid < 32) sB[tid] = b[tid];

    int iy0 = oy0 * 2 - 2, ix0 = ox0 * 2 - 2;
    for (int i = tid; i < 3 * 35 * 67; i += 256) {
        int c = i / (35 * 67), r = i % (35 * 67);
        int iy = r / 67, ix = r % 67;
        int gy = iy0 + iy, gx = ix0 + ix;
        float v = 0.f;
        if ((unsigned)gy < 256u && (unsigned)gx < 256u)
            v = img[((n * 256 + gy) * 256 + gx) * 3 + c];
        sIn[i] = v;
    }
    __syncthreads();

    int ox = tid & 31, oyr = tid >> 5;   // oyr in [0,8)
    float accA[32], accB[32];
#pragma unroll
    for (int o = 0; o < 32; o++) { accA[o] = sB[o]; accB[o] = sB[o]; }

    for (int c = 0; c < 3; c++)
        for (int kh = 0; kh < 5; kh++) {
            const float* rA = &sIn[c * (35 * 67) + (oyr * 2 + kh) * 67 + ox * 2];
            const float* rB = rA + 16 * 67;
#pragma unroll
            for (int kw = 0; kw < 5; kw++) {
                float vA = rA[kw], vB = rB[kw];
                const float* wp = &sW[((c * 5 + kh) * 5 + kw) * 32];
#pragma unroll
                for (int o = 0; o < 32; o++) {
                    accA[o] = fmaf(vA, wp[o], accA[o]);
                    accB[o] = fmaf(vB, wp[o], accB[o]);
                }
            }
        }

    int gyA = oy0 + oyr, gyB = gyA + 8, gx = ox0 + ox;
#pragma unroll
    for (int o = 0; o < 32; o++) {
        g_h1[((n * 32 + o) * 128 + gyA) * 128 + gx] = fmaxf(accA[o], 0.f);
        g_h1[((n * 32 + o) * 128 + gyB) * 128 + gx] = fmaxf(accB[o], 0.f);
    }
}

// =================== conv2: 32->32, k5, s2, p2 ===================
// 32x16 tile, 2 px/thread, double-buffered input+weights, reg prefetch, 1 sync/ic.
__global__ void __launch_bounds__(256, 2)
conv2_kernel(const float* __restrict__ w, const float* __restrict__ b) {
    __shared__ float sIn[2][35 * 67];    // 2345 each
    __shared__ float sW[2][800];
    __shared__ float sB[32];
    int n = blockIdx.z;
    int ox0 = blockIdx.x * 32, oy0 = blockIdx.y * 16;
    int tid = threadIdx.x;
    int ox = tid & 31, oyr = tid >> 5;
    if (tid < 32) sB[tid] = b[tid];

    int iy0 = oy0 * 2 - 2, ix0 = ox0 * 2 - 2;

    float pin[10], pw[4];
    // prefetch ic=0
    {
        const float* src = &g_h1[(n * 32 + 0) * 16384];
#pragma unroll
        for (int j = 0; j < 10; j++) {
            int i = tid + j * 256; float v = 0.f;
            if (i < 2345) {
                int iy = i / 67, ix = i % 67;
                int gy = iy0 + iy, gx = ix0 + ix;
                if ((unsigned)gy < 128u && (unsigned)gx < 128u) v = src[gy * 128 + gx];
            }
            pin[j] = v;
        }
#pragma unroll
        for (int j = 0; j < 4; j++) {
            int i = tid + j * 256; float v = 0.f;
            if (i < 800) { int o = i & 31, tap = i >> 5; v = w[(o * 32 + 0) * 25 + tap]; }
            pw[j] = v;
        }
    }
#pragma unroll
    for (int j = 0; j < 10; j++) { int i = tid + j * 256; if (i < 2345) sIn[0][i] = pin[j]; }
#pragma unroll
    for (int j = 0; j < 4; j++) { int i = tid + j * 256; if (i < 800) sW[0][i] = pw[j]; }
    __syncthreads();

    float accA[32], accB[32];
#pragma unroll
    for (int o = 0; o < 32; o++) { accA[o] = sB[o]; accB[o] = sB[o]; }

    for (int ic = 0; ic < 32; ic++) {
        int cur = ic & 1;
        // prefetch next ic into registers (overlaps with compute below)
        if (ic < 31) {
            const float* src = &g_h1[(n * 32 + ic + 1) * 16384];
#pragma unroll
            for (int j = 0; j < 10; j++) {
                int i = tid + j * 256; float v = 0.f;
                if (i < 2345) {
                    int iy = i / 67, ix = i % 67;
                    int gy = iy0 + iy, gx = ix0 + ix;
                    if ((unsigned)gy < 128u && (unsigned)gx < 128u) v = src[gy * 128 + gx];
                }
                pin[j] = v;
            }
#pragma unroll
            for (int j = 0; j < 4; j++) {
                int i = tid + j * 256; float v = 0.f;
                if (i < 800) { int o = i & 31, tap = i >> 5; v = w[(o * 32 + ic + 1) * 25 + tap]; }
                pw[j] = v;
            }
        }
        // compute current ic
        for (int kh = 0; kh < 5; kh++) {
            const float* rA = &sIn[cur][(oyr * 2 + kh) * 67 + ox * 2];
            const float* rB = rA + 16 * 67;
#pragma unroll
            for (int kw = 0; kw < 5; kw++) {
                float vA = rA[kw], vB = rB[kw];
                const float* wp = &sW[cur][(kh * 5 + kw) * 32];
#pragma unroll
                for (int o = 0; o < 32; o++) {
                    accA[o] = fmaf(vA, wp[o], accA[o]);
                    accB[o] = fmaf(vB, wp[o], accB[o]);
                }
            }
        }
        if (ic < 31) {
#pragma unroll
            for (int j = 0; j < 10; j++) { int i = tid + j * 256; if (i < 2345) sIn[1 - cur][i] = pin[j]; }
#pragma unroll
            for (int j = 0; j < 4; j++) { int i = tid + j * 256; if (i < 800) sW[1 - cur][i] = pw[j]; }
        }
        __syncthreads();
    }

    int gyA = oy0 + oyr, gyB = gyA + 8, gx = ox0 + ox;
#pragma unroll
    for (int o = 0; o < 32; o++) {
        g_h2[((n * 32 + o) * 64 + gyA) * 64 + gx] = fmaxf(accA[o], 0.f);
        g_h2[((n * 32 + o) * 64 + gyB) * 64 + gx] = fmaxf(accB[o], 0.f);
    }
}

// =================== cross-conv: per-sample depthwise k5 p2 ===================
__global__ void xconv_kernel() {
    __shared__ float sIn[68 * 68];
    __shared__ float sK[25];
    int c = blockIdx.x, n = blockIdx.y;
    int tid = threadIdx.x;
    const float* src = &g_h2[(n * 32 + c) * 4096];
    for (int i = tid; i < 68 * 68; i += 256) {
        int iy = i / 68, ix = i % 68;
        int gy = iy - 2, gx = ix - 2;
        sIn[i] = ((unsigned)gy < 64u && (unsigned)gx < 64u) ? src[gy * 64 + gx] : 0.f;
    }
    if (tid < 25) sK[tid] = g_ker[(n * 32 + c) * 25 + tid];
    __syncthreads();
    float k[25];
#pragma unroll
    for (int t = 0; t < 25; t++) k[t] = sK[t];
    for (int p = tid; p < 4096; p += 256) {
        int y = p >> 6, x = p & 63;
        float acc = 0.f;
#pragma unroll
        for (int kh = 0; kh < 5; kh++)
#pragma unroll
            for (int kw = 0; kw < 5; kw++)
                acc = fmaf(sIn[(y + kh) * 68 + (x + kw)], k[kh * 5 + kw], acc);
        g_sa[(n * 32 + c) * 4096 + p] = acc;
    }
}

// =================== mp1: 32->32, k3, p1, relu ===================
// 32x16 tile, 2 px/thread, double-buffered, reg prefetch, 1 sync/ic.
__global__ void __launch_bounds__(256, 2)
mp1_kernel(const float* __restrict__ w, const float* __restrict__ b) {
    __shared__ float sIn[2][18 * 34];    // 612 each
    __shared__ float sW[2][288];
    __shared__ float sB[32];
    int n = blockIdx.z;
    int ox0 = blockIdx.x * 32, oy0 = blockIdx.y * 16;
    int tid = threadIdx.x;
    int ox = tid & 31, oyr = tid >> 5;
    if (tid < 32) sB[tid] = b[tid];

    int iy0 = oy0 - 1, ix0 = ox0 - 1;

    float pin[3], pw[2];
    {
        const float* src = &g_sa[(n * 32 + 0) * 4096];
#pragma unroll
        for (int j = 0; j < 3; j++) {
            int i = tid + j * 256; float v = 0.f;
            if (i < 612) {
                int iy = i / 34, ix = i % 34;
                int gy = iy0 + iy, gx = ix0 + ix;
                if ((unsigned)gy < 64u && (unsigned)gx < 64u) v = src[gy * 64 + gx];
            }
            pin[j] = v;
        }
#pragma unroll
        for (int j = 0; j < 2; j++) {
            int i = tid + j * 256; float v = 0.f;
            if (i < 288) { int o = i & 31, tap = i >> 5; v = w[(o * 32 + 0) * 9 + tap]; }
            pw[j] = v;
        }
    }
#pragma unroll
    for (int j = 0; j < 3; j++) { int i = tid + j * 256; if (i < 612) sIn[0][i] = pin[j]; }
#pragma unroll
    for (int j = 0; j < 2; j++) { int i = tid + j * 256; if (i < 288) sW[0][i] = pw[j]; }
    __syncthreads();

    float accA[32], accB[32];
#pragma unroll
    for (int o = 0; o < 32; o++) { accA[o] = sB[o]; accB[o] = sB[o]; }

    for (int ic = 0; ic < 32; ic++) {
        int cur = ic & 1;
        if (ic < 31) {
            const float* src = &g_sa[(n * 32 + ic + 1) * 4096];
#pragma unroll
            for (int j = 0; j < 3; j++) {
                int i = tid + j * 256; float v = 0.f;
                if (i < 612) {
                    int iy = i / 34, ix = i % 34;
                    int gy = iy0 + iy, gx = ix0 + ix;
                    if ((unsigned)gy < 64u && (unsigned)gx < 64u) v = src[gy * 64 + gx];
                }
                pin[j] = v;
            }
#pragma unroll
            for (int j = 0; j < 2; j++) {
                int i = tid + j * 256; float v = 0.f;
                if (i < 288) { int o = i & 31, tap = i >> 5; v = w[(o * 32 + ic + 1) * 9 + tap]; }
                pw[j] = v;
            }
        }
#pragma unroll
        for (int kh = 0; kh < 3; kh++) {
            const float* rA = &sIn[cur][(oyr + kh) * 34 + ox];
            const float* rB = rA + 8 * 34;
#pragma unroll
            for (int kw = 0; kw < 3; kw++) {
                float vA = rA[kw], vB = rB[kw];
                const float* wp = &sW[cur][(kh * 3 + kw) * 32];
#pragma unroll
                for (int o = 0; o < 32; o++) {
                    accA[o] = fmaf(vA, wp[o], accA[o]);
                    accB[o] = fmaf(vB, wp[o], accB[o]);
                }
            }
        }
        if (ic < 31) {
#pragma unroll
            for (int j = 0; j < 3; j++) { int i = tid + j * 256; if (i < 612) sIn[1 - cur][i] = pin[j]; }
#pragma unroll
            for (int j = 0; j < 2; j++) { int i = tid + j * 256; if (i < 288) sW[1 - cur][i] = pw[j]; }
        }
        __syncthreads();
    }

    int gyA = oy0 + oyr, gyB = gyA + 8, gx = ox0 + ox;
#pragma unroll
    for (int o = 0; o < 32; o++) {
        g_f[((n * 32 + o) * 64 + gyA) * 64 + gx] = fmaxf(accA[o], 0.f);
        g_f[((n * 32 + o) * 64 + gyB) * 64 + gx] = fmaxf(accB[o], 0.f);
    }
}

// =================== mp2: 32->2, k3, p1 ===================
// 32x8 tile, double-buffered, reg prefetch, 1 sync/ic.
__global__ void __launch_bounds__(256, 2)
mp2_kernel(const float* __restrict__ w, const float* __restrict__ b,
           float* __restrict__ out) {
    __shared__ float sIn[2][10 * 34];    // 340 each
    __shared__ float sW[2][18];
    int n = blockIdx.z;
    int ox0 = blockIdx.x * 32, oy0 = blockIdx.y * 8;
    int tid = threadIdx.x;
    int ox = tid & 31, oy = tid >> 5;

    int iy0 = oy0 - 1, ix0 = ox0 - 1;

    float pin[2], pwv;
    {
        const float* src = &g_f[(n * 32 + 0) * 4096];
#pragma unroll
        for (int j = 0; j < 2; j++) {
            int i = tid + j * 256; float v = 0.f;
            if (i < 340) {
                int iy = i / 34, ix = i % 34;
                int gy = iy0 + iy, gx = ix0 + ix;
                if ((unsigned)gy < 64u && (unsigned)gx < 64u) v = src[gy * 64 + gx];
            }
            pin[j] = v;
        }
        pwv = (tid < 18) ? w[((tid & 1) * 32 + 0) * 9 + (tid >> 1)] : 0.f;
    }
#pragma unroll
    for (int j = 0; j < 2; j++) { int i = tid + j * 256; if (i < 340) sIn[0][i] = pin[j]; }
    if (tid < 18) sW[0][tid] = pwv;
    __syncthreads();

    float acc0 = b[0], acc1 = b[1];
    for (int ic = 0; ic < 32; ic++) {
        int cur = ic & 1;
        if (ic < 31) {
            const float* src = &g_f[(n * 32 + ic + 1) * 4096];
#pragma unroll
            for (int j = 0; j < 2; j++) {
                int i = tid + j * 256; float v = 0.f;
                if (i < 340) {
                    int iy = i / 34, ix = i % 34;
                    int gy = iy0 + iy, gx = ix0 + ix;
                    if ((unsigned)gy < 64u && (unsigned)gx < 64u) v = src[gy * 64 + gx];
                }
                pin[j] = v;
            }
            pwv = (tid < 18) ? w[((tid & 1) * 32 + ic + 1) * 9 + (tid >> 1)] : 0.f;
        }
#pragma unroll
        for (int kh = 0; kh < 3; kh++) {
            const float* row = &sIn[cur][(oy + kh) * 34 + ox];
#pragma unroll
            for (int kw = 0; kw < 3; kw++) {
                float v = row[kw];
                acc0 = fmaf(v, sW[cur][(kh * 3 + kw) * 2 + 0], acc0);
                acc1 = fmaf(v, sW[cur][(kh * 3 + kw) * 2 + 1], acc1);
            }
        }
        if (ic < 31) {
#pragma unroll
            for (int j = 0; j < 2; j++) { int i = tid + j * 256; if (i < 340) sIn[1 - cur][i] = pin[j]; }
            if (tid < 18) sW[1 - cur][tid] = pwv;
        }
        __syncthreads();
    }
    int gy = oy0 + oy, gx = ox0 + ox;
    out[((n * 2 + 0) * 64 + gy) * 64 + gx] = acc0;
    out[((n * 2 + 1) * 64 + gy) * 64 + gx] = acc1;
}

// =================== launch ===================
extern "C" void kernel_launch(void* const* d_in, const int* in_sizes, int n_in,
                              void* d_out, int out_size) {
    const float* images = (const float*)d_in[0];
    const float* actions = (const float*)d_in[1];
    const float* pe_w1 = (const float*)d_in[2];
    const float* pe_b1 = (const float*)d_in[3];
    const float* pe_w2 = (const float*)d_in[4];
    const float* pe_b2 = (const float*)d_in[5];
    const float* ae_w1 = (const float*)d_in[6];
    const float* ae_b1 = (const float*)d_in[7];
    const float* ae_w2 = (const float*)d_in[8];
    const float* ae_b2 = (const float*)d_in[9];
    const float* mp_w1 = (const float*)d_in[10];
    const float* mp_b1 = (const float*)d_in[11];
    const float* mp_w2 = (const float*)d_in[12];
    const float* mp_b2 = (const float*)d_in[13];
    float* out = (float*)d_out;

    ae_kernel<<<NB, 256>>>(actions, ae_w1, ae_b1, ae_w2, ae_b2);
    conv1_kernel<<<dim3(4, 8, NB), 256>>>(images, pe_w1, pe_b1);
    conv2_kernel<<<dim3(2, 4, NB), 256>>>(pe_w2, pe_b2);
    xconv_kernel<<<dim3(32, NB), 256>>>();
    mp1_kernel<<<dim3(2, 4, NB), 256>>>(mp_w1, mp_b1);
    mp2_kernel<<<dim3(2, 8, NB), 256>>>(mp_w2, mp_b2, out);
}

// round 3
// speedup vs baseline: 1.6760x; 1.1320x over previous
#include <cuda_runtime.h>
#include <cuda_bf16.h>
#include <cstdint>

#define NB 64
#define CC 32
#define KK 5
#define ADIM 4
#define AHID 256

// packed f32x2 helpers (sm_100+): one instruction = 2 fp32 FMAs per lane
#define PACK2(out, lo, hi) \
    asm("mov.b64 %0, {%1, %2};" : "=l"(out) : "r"(lo), "r"(hi))
#define FMA2(acc, a, b) \
    asm("fma.rn.f32x2 %0, %1, %2, %0;" : "+l"(acc) : "l"(a), "l"(b))
#define UNPACK2(lo, hi, in) \
    asm("mov.b64 {%0, %1}, %2;" : "=r"(lo), "=r"(hi) : "l"(in))

__device__ __forceinline__ unsigned long long pack_dup(float v) {
    unsigned long long r; unsigned u = __float_as_uint(v);
    PACK2(r, u, u); return r;
}

// ---------------- scratch ----------------
__device__ float g_h1[NB * CC * 128 * 128];
__device__ float g_h2[NB * CC * 64 * 64];
__device__ float g_ker[NB * CC * KK * KK];
__device__ float g_sa[NB * CC * 64 * 64];
__device__ float g_f [NB * CC * 64 * 64];

// =================== action encoder MLP ===================
__global__ void ae_kernel(const float* __restrict__ act,
                          const float* __restrict__ w1, const float* __restrict__ b1,
                          const float* __restrict__ w2, const float* __restrict__ b2) {
    __shared__ float sH[AHID];
    __shared__ float sA[ADIM];
    int n = blockIdx.x, tid = threadIdx.x;
    if (tid < ADIM) sA[tid] = act[n * ADIM + tid];
    __syncthreads();
    float h = b1[tid];
#pragma unroll
    for (int i = 0; i < ADIM; i++) h = fmaf(sA[i], w1[i * AHID + tid], h);
    sH[tid] = fmaxf(h, 0.f);
    __syncthreads();
    for (int o = tid; o < CC * KK * KK; o += 256) {
        float acc = b2[o];
#pragma unroll 8
        for (int j = 0; j < AHID; j++) acc = fmaf(sH[j], w2[j * (CC * KK * KK) + o], acc);
        g_ker[n * (CC * KK * KK) + o] = acc;
    }
}

// =================== conv1: 3->32, k5, s2, p2, NHWC in ===================
__global__ void __launch_bounds__(256, 2)
conv1_kernel(const float* __restrict__ img,
             const float* __restrict__ w, const float* __restrict__ b) {
    __shared__ __align__(8) float sIn[3 * 35 * 67];
    __shared__ __align__(8) float sW[75 * 32];
    __shared__ __align__(8) float sB[32];
    int n = blockIdx.z;
    int ox0 = blockIdx.x * 32, oy0 = blockIdx.y * 16;
    int tid = threadIdx.x;

    for (int i = tid; i < 75 * 32; i += 256) {
        int o = i & 31, tap = i >> 5;
        int c = tap / 25, r = tap % 25, kh = r / 5, kw = r % 5;
        sW[i] = w[((o * 3 + c) * 5 + kh) * 5 + kw];
    }
    if (tid < 32) sB[tid] = b[tid];

    int iy0 = oy0 * 2 - 2, ix0 = ox0 * 2 - 2;
    for (int i = tid; i < 3 * 35 * 67; i += 256) {
        int c = i / (35 * 67), r = i % (35 * 67);
        int iy = r / 67, ix = r % 67;
        int gy = iy0 + iy, gx = ix0 + ix;
        float v = 0.f;
        if ((unsigned)gy < 256u && (unsigned)gx < 256u)
            v = img[((n * 256 + gy) * 256 + gx) * 3 + c];
        sIn[i] = v;
    }
    __syncthreads();

    int ox = tid & 31, oyr = tid >> 5;
    unsigned long long accA[16], accB[16];
    const unsigned long long* sB2 = (const unsigned long long*)sB;
#pragma unroll
    for (int o = 0; o < 16; o++) { accA[o] = sB2[o]; accB[o] = sB2[o]; }

    for (int c = 0; c < 3; c++)
        for (int kh = 0; kh < 5; kh++) {
            const float* rA = &sIn[c * (35 * 67) + (oyr * 2 + kh) * 67 + ox * 2];
            const float* rB = rA + 16 * 67;
#pragma unroll
            for (int kw = 0; kw < 5; kw++) {
                unsigned long long vA2 = pack_dup(rA[kw]);
                unsigned long long vB2 = pack_dup(rB[kw]);
                const unsigned long long* wp =
                    (const unsigned long long*)&sW[((c * 5 + kh) * 5 + kw) * 32];
#pragma unroll
                for (int o = 0; o < 16; o++) {
                    unsigned long long w2 = wp[o];
                    FMA2(accA[o], vA2, w2);
                    FMA2(accB[o], vB2, w2);
                }
            }
        }

    int gyA = oy0 + oyr, gyB = gyA + 8, gx = ox0 + ox;
#pragma unroll
    for (int o = 0; o < 16; o++) {
        unsigned lo, hi;
        UNPACK2(lo, hi, accA[o]);
        g_h1[((n * 32 + 2 * o) * 128 + gyA) * 128 + gx] = fmaxf(__uint_as_float(lo), 0.f);
        g_h1[((n * 32 + 2 * o + 1) * 128 + gyA) * 128 + gx] = fmaxf(__uint_as_float(hi), 0.f);
        UNPACK2(lo, hi, accB[o]);
        g_h1[((n * 32 + 2 * o) * 128 + gyB) * 128 + gx] = fmaxf(__uint_as_float(lo), 0.f);
        g_h1[((n * 32 + 2 * o + 1) * 128 + gyB) * 128 + gx] = fmaxf(__uint_as_float(hi), 0.f);
    }
}

// =================== conv2: 32->32, k5, s2, p2 ===================
__global__ void __launch_bounds__(256, 2)
conv2_kernel(const float* __restrict__ w, const float* __restrict__ b) {
    __shared__ __align__(8) float sIn[2][35 * 67];
    __shared__ __align__(8) float sW[2][800];
    __shared__ __align__(8) float sB[32];
    int n = blockIdx.z;
    int ox0 = blockIdx.x * 32, oy0 = blockIdx.y * 16;
    int tid = threadIdx.x;
    int ox = tid & 31, oyr = tid >> 5;
    if (tid < 32) sB[tid] = b[tid];

    int iy0 = oy0 * 2 - 2, ix0 = ox0 * 2 - 2;

    float pin[10], pw[4];
    {
        const float* src = &g_h1[(n * 32 + 0) * 16384];
#pragma unroll
        for (int j = 0; j < 10; j++) {
            int i = tid + j * 256; float v = 0.f;
            if (i < 2345) {
                int iy = i / 67, ix = i % 67;
                int gy = iy0 + iy, gx = ix0 + ix;
                if ((unsigned)gy < 128u && (unsigned)gx < 128u) v = src[gy * 128 + gx];
            }
            pin[j] = v;
        }
#pragma unroll
        for (int j = 0; j < 4; j++) {
            int i = tid + j * 256; float v = 0.f;
            if (i < 800) { int o = i & 31, tap = i >> 5; v = w[(o * 32 + 0) * 25 + tap]; }
            pw[j] = v;
        }
    }
#pragma unroll
    for (int j = 0; j < 10; j++) { int i = tid + j * 256; if (i < 2345) sIn[0][i] = pin[j]; }
#pragma unroll
    for (int j = 0; j < 4; j++) { int i = tid + j * 256; if (i < 800) sW[0][i] = pw[j]; }
    __syncthreads();

    unsigned long long accA[16], accB[16];
    const unsigned long long* sB2 = (const unsigned long long*)sB;
#pragma unroll
    for (int o = 0; o < 16; o++) { accA[o] = sB2[o]; accB[o] = sB2[o]; }

    for (int ic = 0; ic < 32; ic++) {
        int cur = ic & 1;
        if (ic < 31) {
            const float* src = &g_h1[(n * 32 + ic + 1) * 16384];
#pragma unroll
            for (int j = 0; j < 10; j++) {
                int i = tid + j * 256; float v = 0.f;
                if (i < 2345) {
                    int iy = i / 67, ix = i % 67;
                    int gy = iy0 + iy, gx = ix0 + ix;
                    if ((unsigned)gy < 128u && (unsigned)gx < 128u) v = src[gy * 128 + gx];
                }
                pin[j] = v;
            }
#pragma unroll
            for (int j = 0; j < 4; j++) {
                int i = tid + j * 256; float v = 0.f;
                if (i < 800) { int o = i & 31, tap = i >> 5; v = w[(o * 32 + ic + 1) * 25 + tap]; }
                pw[j] = v;
            }
        }
        for (int kh = 0; kh < 5; kh++) {
            const float* rA = &sIn[cur][(oyr * 2 + kh) * 67 + ox * 2];
            const float* rB = rA + 16 * 67;
#pragma unroll
            for (int kw = 0; kw < 5; kw++) {
                unsigned long long vA2 = pack_dup(rA[kw]);
                unsigned long long vB2 = pack_dup(rB[kw]);
                const unsigned long long* wp =
                    (const unsigned long long*)&sW[cur][(kh * 5 + kw) * 32];
#pragma unroll
                for (int o = 0; o < 16; o++) {
                    unsigned long long w2 = wp[o];
                    FMA2(accA[o], vA2, w2);
                    FMA2(accB[o], vB2, w2);
                }
            }
        }
        if (ic < 31) {
#pragma unroll
            for (int j = 0; j < 10; j++) { int i = tid + j * 256; if (i < 2345) sIn[1 - cur][i] = pin[j]; }
#pragma unroll
            for (int j = 0; j < 4; j++) { int i = tid + j * 256; if (i < 800) sW[1 - cur][i] = pw[j]; }
        }
        __syncthreads();
    }

    int gyA = oy0 + oyr, gyB = gyA + 8, gx = ox0 + ox;
#pragma unroll
    for (int o = 0; o < 16; o++) {
        unsigned lo, hi;
        UNPACK2(lo, hi, accA[o]);
        g_h2[((n * 32 + 2 * o) * 64 + gyA) * 64 + gx] = fmaxf(__uint_as_float(lo), 0.f);
        g_h2[((n * 32 + 2 * o + 1) * 64 + gyA) * 64 + gx] = fmaxf(__uint_as_float(hi), 0.f);
        UNPACK2(lo, hi, accB[o]);
        g_h2[((n * 32 + 2 * o) * 64 + gyB) * 64 + gx] = fmaxf(__uint_as_float(lo), 0.f);
        g_h2[((n * 32 + 2 * o + 1) * 64 + gyB) * 64 + gx] = fmaxf(__uint_as_float(hi), 0.f);
    }
}

// =================== cross-conv: per-sample depthwise k5 p2 ===================
__global__ void xconv_kernel() {
    __shared__ float sIn[68 * 68];
    __shared__ float sK[25];
    int c = blockIdx.x, n = blockIdx.y;
    int tid = threadIdx.x;
    const float* src = &g_h2[(n * 32 + c) * 4096];
    for (int i = tid; i < 68 * 68; i += 256) {
        int iy = i / 68, ix = i % 68;
        int gy = iy - 2, gx = ix - 2;
        sIn[i] = ((unsigned)gy < 64u && (unsigned)gx < 64u) ? src[gy * 64 + gx] : 0.f;
    }
    if (tid < 25) sK[tid] = g_ker[(n * 32 + c) * 25 + tid];
    __syncthreads();
    float k[25];
#pragma unroll
    for (int t = 0; t < 25; t++) k[t] = sK[t];
    for (int p = tid; p < 4096; p += 256) {
        int y = p >> 6, x = p & 63;
        float acc = 0.f;
#pragma unroll
        for (int kh = 0; kh < 5; kh++)
#pragma unroll
            for (int kw = 0; kw < 5; kw++)
                acc = fmaf(sIn[(y + kh) * 68 + (x + kw)], k[kh * 5 + kw], acc);
        g_sa[(n * 32 + c) * 4096 + p] = acc;
    }
}

// =================== mp1: 32->32, k3, p1, relu ===================
__global__ void __launch_bounds__(256, 2)
mp1_kernel(const float* __restrict__ w, const float* __restrict__ b) {
    __shared__ __align__(8) float sIn[2][18 * 34];
    __shared__ __align__(8) float sW[2][288];
    __shared__ __align__(8) float sB[32];
    int n = blockIdx.z;
    int ox0 = blockIdx.x * 32, oy0 = blockIdx.y * 16;
    int tid = threadIdx.x;
    int ox = tid & 31, oyr = tid >> 5;
    if (tid < 32) sB[tid] = b[tid];

    int iy0 = oy0 - 1, ix0 = ox0 - 1;

    float pin[3], pw[2];
    {
        const float* src = &g_sa[(n * 32 + 0) * 4096];
#pragma unroll
        for (int j = 0; j < 3; j++) {
            int i = tid + j * 256; float v = 0.f;
            if (i < 612) {
                int iy = i / 34, ix = i % 34;
                int gy = iy0 + iy, gx = ix0 + ix;
                if ((unsigned)gy < 64u && (unsigned)gx < 64u) v = src[gy * 64 + gx];
            }
            pin[j] = v;
        }
#pragma unroll
        for (int j = 0; j < 2; j++) {
            int i = tid + j * 256; float v = 0.f;
            if (i < 288) { int o = i & 31, tap = i >> 5; v = w[(o * 32 + 0) * 9 + tap]; }
            pw[j] = v;
        }
    }
#pragma unroll
    for (int j = 0; j < 3; j++) { int i = tid + j * 256; if (i < 612) sIn[0][i] = pin[j]; }
#pragma unroll
    for (int j = 0; j < 2; j++) { int i = tid + j * 256; if (i < 288) sW[0][i] = pw[j]; }
    __syncthreads();

    unsigned long long accA[16], accB[16];
    const unsigned long long* sB2 = (const unsigned long long*)sB;
#pragma unroll
    for (int o = 0; o < 16; o++) { accA[o] = sB2[o]; accB[o] = sB2[o]; }

    for (int ic = 0; ic < 32; ic++) {
        int cur = ic & 1;
        if (ic < 31) {
            const float* src = &g_sa[(n * 32 + ic + 1) * 4096];
#pragma unroll
            for (int j = 0; j < 3; j++) {
                int i = tid + j * 256; float v = 0.f;
                if (i < 612) {
                    int iy = i / 34, ix = i % 34;
                    int gy = iy0 + iy, gx = ix0 + ix;
                    if ((unsigned)gy < 64u && (unsigned)gx < 64u) v = src[gy * 64 + gx];
                }
                pin[j] = v;
            }
#pragma unroll
            for (int j = 0; j < 2; j++) {
                int i = tid + j * 256; float v = 0.f;
                if (i < 288) { int o = i & 31, tap = i >> 5; v = w[(o * 32 + ic + 1) * 9 + tap]; }
                pw[j] = v;
            }
        }
#pragma unroll
        for (int kh = 0; kh < 3; kh++) {
            const float* rA = &sIn[cur][(oyr + kh) * 34 + ox];
            const float* rB = rA + 8 * 34;
#pragma unroll
            for (int kw = 0; kw < 3; kw++) {
                unsigned long long vA2 = pack_dup(rA[kw]);
                unsigned long long vB2 = pack_dup(rB[kw]);
                const unsigned long long* wp =
                    (const unsigned long long*)&sW[cur][(kh * 3 + kw) * 32];
#pragma unroll
                for (int o = 0; o < 16; o++) {
                    unsigned long long w2 = wp[o];
                    FMA2(accA[o], vA2, w2);
                    FMA2(accB[o], vB2, w2);
                }
            }
        }
        if (ic < 31) {
#pragma unroll
            for (int j = 0; j < 3; j++) { int i = tid + j * 256; if (i < 612) sIn[1 - cur][i] = pin[j]; }
#pragma unroll
            for (int j = 0; j < 2; j++) { int i = tid + j * 256; if (i < 288) sW[1 - cur][i] = pw[j]; }
        }
        __syncthreads();
    }

    int gyA = oy0 + oyr, gyB = gyA + 8, gx = ox0 + ox;
#pragma unroll
    for (int o = 0; o < 16; o++) {
        unsigned lo, hi;
        UNPACK2(lo, hi, accA[o]);
        g_f[((n * 32 + 2 * o) * 64 + gyA) * 64 + gx] = fmaxf(__uint_as_float(lo), 0.f);
        g_f[((n * 32 + 2 * o + 1) * 64 + gyA) * 64 + gx] = fmaxf(__uint_as_float(hi), 0.f);
        UNPACK2(lo, hi, accB[o]);
        g_f[((n * 32 + 2 * o) * 64 + gyB) * 64 + gx] = fmaxf(__uint_as_float(lo), 0.f);
        g_f[((n * 32 + 2 * o + 1) * 64 + gyB) * 64 + gx] = fmaxf(__uint_as_float(hi), 0.f);
    }
}

// =================== mp2: 32->2, k3, p1 ===================
// packs the 2 output channels into one f32x2 accumulator per pixel
__global__ void __launch_bounds__(256, 2)
mp2_kernel(const float* __restrict__ w, const float* __restrict__ b,
           float* __restrict__ out) {
    __shared__ __align__(8) float sIn[2][10 * 34];
    __shared__ __align__(8) float sW[2][18];
    int n = blockIdx.z;
    int ox0 = blockIdx.x * 32, oy0 = blockIdx.y * 8;
    int tid = threadIdx.x;
    int ox = tid & 31, oy = tid >> 5;

    int iy0 = oy0 - 1, ix0 = ox0 - 1;

    float pin[2], pwv;
    {
        const float* src = &g_f[(n * 32 + 0) * 4096];
#pragma unroll
        for (int j = 0; j < 2; j++) {
            int i = tid + j * 256; float v = 0.f;
            if (i < 340) {
                int iy = i / 34, ix = i % 34;
                int gy = iy0 + iy, gx = ix0 + ix;
                if ((unsigned)gy < 64u && (unsigned)gx < 64u) v = src[gy * 64 + gx];
            }
            pin[j] = v;
        }
        pwv = (tid < 18) ? w[((tid & 1) * 32 + 0) * 9 + (tid >> 1)] : 0.f;
    }
#pragma unroll
    for (int j = 0; j < 2; j++) { int i = tid + j * 256; if (i < 340) sIn[0][i] = pin[j]; }
    if (tid < 18) sW[0][tid] = pwv;
    __syncthreads();

    unsigned long long acc2;
    PACK2(acc2, __float_as_uint(b[0]), __float_as_uint(b[1]));

    for (int ic = 0; ic < 32; ic++) {
        int cur = ic & 1;
        if (ic < 31) {
            const float* src = &g_f[(n * 32 + ic + 1) * 4096];
#pragma unroll
            for (int j = 0; j < 2; j++) {
                int i = tid + j * 256; float v = 0.f;
                if (i < 340) {
                    int iy = i / 34, ix = i % 34;
                    int gy = iy0 + iy, gx = ix0 + ix;
                    if ((unsigned)gy < 64u && (unsigned)gx < 64u) v = src[gy * 64 + gx];
                }
                pin[j] = v;
            }
            pwv = (tid < 18) ? w[((tid & 1) * 32 + ic + 1) * 9 + (tid >> 1)] : 0.f;
        }
        const unsigned long long* wp2 = (const unsigned long long*)&sW[cur][0];
#pragma unroll
        for (int kh = 0; kh < 3; kh++) {
            const float* row = &sIn[cur][(oy + kh) * 34 + ox];
#pragma unroll
            for (int kw = 0; kw < 3; kw++) {
                unsigned long long v2 = pack_dup(row[kw]);
                FMA2(acc2, v2, wp2[kh * 3 + kw]);
            }
        }
        if (ic < 31) {
#pragma unroll
            for (int j = 0; j < 2; j++) { int i = tid + j * 256; if (i < 340) sIn[1 - cur][i] = pin[j]; }
            if (tid < 18) sW[1 - cur][tid] = pwv;
        }
        __syncthreads();
    }
    int gy = oy0 + oy, gx = ox0 + ox;
    unsigned lo, hi;
    UNPACK2(lo, hi, acc2);
    out[((n * 2 + 0) * 64 + gy) * 64 + gx] = __uint_as_float(lo);
    out[((n * 2 + 1) * 64 + gy) * 64 + gx] = __uint_as_float(hi);
}

// =================== launch ===================
extern "C" void kernel_launch(void* const* d_in, const int* in_sizes, int n_in,
                              void* d_out, int out_size) {
    const float* images = (const float*)d_in[0];
    const float* actions = (const float*)d_in[1];
    const float* pe_w1 = (const float*)d_in[2];
    const float* pe_b1 = (const float*)d_in[3];
    const float* pe_w2 = (const float*)d_in[4];
    const float* pe_b2 = (const float*)d_in[5];
    const float* ae_w1 = (const float*)d_in[6];
    const float* ae_b1 = (const float*)d_in[7];
    const float* ae_w2 = (const float*)d_in[8];
    const float* ae_b2 = (const float*)d_in[9];
    const float* mp_w1 = (const float*)d_in[10];
    const float* mp_b1 = (const float*)d_in[11];
    const float* mp_w2 = (const float*)d_in[12];
    const float* mp_b2 = (const float*)d_in[13];
    float* out = (float*)d_out;

    ae_kernel<<<NB, 256>>>(actions, ae_w1, ae_b1, ae_w2, ae_b2);
    conv1_kernel<<<dim3(4, 8, NB), 256>>>(images, pe_w1, pe_b1);
    conv2_kernel<<<dim3(2, 4, NB), 256>>>(pe_w2, pe_b2);
    xconv_kernel<<<dim3(32, NB), 256>>>();
    mp1_kernel<<<dim3(2, 4, NB), 256>>>(mp_w1, mp_b1);
    mp2_kernel<<<dim3(2, 8, NB), 256>>>(mp_w2, mp_b2, out);
}